// round 4
// baseline (speedup 1.0000x reference)
#include <cuda_runtime.h>
#include <cuda_bf16.h>
#include <cstdint>

// Embedding gather: out[i, :] = embeddings[x[i], :]
// x: int32 [8192], embeddings: fp32 [32000, 1024], out: fp32 [8192, 1024]
//
// Deep-ring DMA: 1 CTA per SM, 48-stage 4KB ring in 192KB dynamic SMEM,
// 40 bulk loads in flight per CTA (160KB/SM of reads outstanding).
// cp.async.bulk GMEM->SMEM (mbarrier) + SMEM->GMEM (bulk groups).

static constexpr int EMBED_DIM  = 1024;
static constexpr int ROW_BYTES  = EMBED_DIM * 4;   // 4096
static constexpr int N_ROWS     = 8192;
static constexpr int GRID       = 148;             // 1 CTA per SM
static constexpr int NSTAGES    = 48;              // 192KB ring (dynamic smem)
static constexpr int LOAD_AHEAD = 40;              // loads in flight per CTA
static constexpr int WG_KEEP    = NSTAGES - LOAD_AHEAD;  // 8 store groups outstanding
static constexpr int MAX_ROWS_PER_CTA = (N_ROWS + GRID - 1) / GRID;  // 56

static constexpr int SMEM_BYTES = NSTAGES * ROW_BYTES;  // ring only (dynamic)

static __device__ __forceinline__ uint32_t s2u(const void* p) {
    return (uint32_t)__cvta_generic_to_shared(p);
}

static __device__ __forceinline__ void mbar_init(uint32_t mbar, uint32_t count) {
    asm volatile("mbarrier.init.shared.b64 [%0], %1;" :: "r"(mbar), "r"(count) : "memory");
}

static __device__ __forceinline__ void mbar_expect_tx(uint32_t mbar, uint32_t bytes) {
    asm volatile("mbarrier.arrive.expect_tx.shared.b64 _, [%0], %1;"
                 :: "r"(mbar), "r"(bytes) : "memory");
}

static __device__ __forceinline__ void mbar_wait(uint32_t mbar, uint32_t parity) {
    uint32_t done;
    asm volatile(
        "{\n\t"
        ".reg .pred p;\n\t"
        "mbarrier.try_wait.parity.shared.b64 p, [%1], %2;\n\t"
        "selp.b32 %0, 1, 0, p;\n\t"
        "}"
        : "=r"(done) : "r"(mbar), "r"(parity) : "memory");
    if (!done) {
        asm volatile(
            "{\n\t"
            ".reg .pred P1;\n\t"
            "WAIT_LOOP_%=:\n\t"
            "mbarrier.try_wait.parity.shared.b64 P1, [%0], %1, 0x989680;\n\t"
            "@P1 bra.uni WAIT_DONE_%=;\n\t"
            "bra.uni WAIT_LOOP_%=;\n\t"
            "WAIT_DONE_%=:\n\t"
            "}"
            :: "r"(mbar), "r"(parity) : "memory");
    }
}

static __device__ __forceinline__ void bulk_g2s(uint32_t dst_smem, const void* src_gmem,
                                                uint32_t bytes, uint32_t mbar) {
    asm volatile(
        "cp.async.bulk.shared::cluster.global.mbarrier::complete_tx::bytes "
        "[%0], [%1], %2, [%3];"
        :: "r"(dst_smem), "l"(src_gmem), "r"(bytes), "r"(mbar) : "memory");
}

static __device__ __forceinline__ void bulk_s2g(void* dst_gmem, uint32_t src_smem,
                                                uint32_t bytes) {
    asm volatile(
        "cp.async.bulk.global.shared::cta.bulk_group [%0], [%1], %2;"
        :: "l"(dst_gmem), "r"(src_smem), "r"(bytes) : "memory");
}

extern __shared__ char ring_buf[];   // NSTAGES * ROW_BYTES

__global__ __launch_bounds__(32, 1)
void embedding_dma_kernel(const int* __restrict__ idx,
                          const float* __restrict__ emb,
                          float* __restrict__ out)
{
    __shared__ alignas(8) uint64_t mbar[NSTAGES];
    __shared__ int sidx[MAX_ROWS_PER_CTA];

    const int bid = blockIdx.x;
    const int t   = threadIdx.x;

    const int n = (N_ROWS - bid + GRID - 1) / GRID;   // 55 or 56 rows

    // Stage this CTA's indices into SMEM (coalesced across CTAs)
    for (int r = t; r < n; r += 32)
        sidx[r] = idx[bid + GRID * r];

    if (t == 0) {
        for (int s = 0; s < NSTAGES; s++)
            mbar_init(s2u(&mbar[s]), 1);
        asm volatile("fence.proxy.async.shared::cta;" ::: "memory");
    }
    __syncwarp();

    if (t != 0) return;   // single orchestrator thread

    const uint32_t buf_base  = s2u(ring_buf);
    const uint32_t mbar_base = s2u(&mbar[0]);

    // Prologue: flood the pipeline with LOAD_AHEAD bulk loads
    const int pro = n < LOAD_AHEAD ? n : LOAD_AHEAD;
    for (int k = 0; k < pro; k++) {
        const uint32_t mb = mbar_base + k * 8;
        mbar_expect_tx(mb, ROW_BYTES);
        bulk_g2s(buf_base + k * ROW_BYTES,
                 emb + (size_t)sidx[k] * EMBED_DIM, ROW_BYTES, mb);
    }

    // Main loop
    for (int k = 0; k < n; k++) {
        const int s  = k % NSTAGES;
        const int ph = (k / NSTAGES) & 1;

        mbar_wait(mbar_base + s * 8, ph);

        bulk_s2g(out + (size_t)(bid + GRID * k) * EMBED_DIM,
                 buf_base + s * ROW_BYTES, ROW_BYTES);
        asm volatile("cp.async.bulk.commit_group;" ::: "memory");

        const int kn = k + LOAD_AHEAD;
        if (kn < n) {
            // Stage (kn % NSTAGES) was last used by row kn-NSTAGES, whose
            // store is commit-group kn-NSTAGES = k-WG_KEEP; keeping WG_KEEP
            // groups outstanding guarantees that group has finished reading.
            asm volatile("cp.async.bulk.wait_group.read %0;" :: "n"(WG_KEEP) : "memory");
            const int sn = kn % NSTAGES;
            const uint32_t mb = mbar_base + sn * 8;
            mbar_expect_tx(mb, ROW_BYTES);
            bulk_g2s(buf_base + sn * ROW_BYTES,
                     emb + (size_t)sidx[kn] * EMBED_DIM, ROW_BYTES, mb);
        }
    }

    // Drain all outstanding stores before exit
    asm volatile("cp.async.bulk.wait_group %0;" :: "n"(0) : "memory");
}

extern "C" void kernel_launch(void* const* d_in, const int* in_sizes, int n_in,
                              void* d_out, int out_size)
{
    const int*   x   = (const int*)d_in[0];          // [4, 2048] int32 indices
    const float* emb = (const float*)d_in[1];        // [32000, 1024] fp32
    float*       out = (float*)d_out;                // [4, 2048, 1024] fp32

    cudaFuncSetAttribute(embedding_dma_kernel,
                         cudaFuncAttributeMaxDynamicSharedMemorySize, SMEM_BYTES);

    embedding_dma_kernel<<<GRID, 32, SMEM_BYTES>>>(x, emb, out);
}

// round 5
// speedup vs baseline: 1.1915x; 1.1915x over previous
#include <cuda_runtime.h>
#include <cuda_bf16.h>
#include <cstdint>

// Embedding gather: out[i, :] = embeddings[x[i], :]
// x: int32 [8192], embeddings: fp32 [32000, 1024], out: fp32 [8192, 1024]
//
// R2 design + cache policy control:
//   - gathers:  ld.global.cg  (L2 only; gathered rows never re-hit in L1)
//   - stores:   st.global.cs  (streaming/evict-first; don't evict the table
//               from L2 — output lines are dead after writeback)

static constexpr int EMBED_DIM    = 1024;
static constexpr int VEC_PER_ROW  = EMBED_DIM / 4;   // 256 float4 per row
static constexpr int ROWS_PER_CTA = 8;

static __device__ __forceinline__ float4 ldcg_f4(const float4* p) {
    float4 v;
    asm volatile("ld.global.cg.v4.f32 {%0,%1,%2,%3}, [%4];"
                 : "=f"(v.x), "=f"(v.y), "=f"(v.z), "=f"(v.w) : "l"(p));
    return v;
}

static __device__ __forceinline__ void stcs_f4(float4* p, float4 v) {
    asm volatile("st.global.cs.v4.f32 [%0], {%1,%2,%3,%4};"
                 :: "l"(p), "f"(v.x), "f"(v.y), "f"(v.z), "f"(v.w) : "memory");
}

__global__ __launch_bounds__(256, 4)
void embedding_gather_kernel(const int* __restrict__ idx,
                             const float4* __restrict__ emb,
                             float4* __restrict__ out)
{
    const int base = blockIdx.x * ROWS_PER_CTA;
    const int t    = threadIdx.x;

    // 8 index loads (one 32B sector, broadcast; L2-hot after first touch)
    long long src[ROWS_PER_CTA];
#pragma unroll
    for (int r = 0; r < ROWS_PER_CTA; r++)
        src[r] = (long long)idx[base + r];

    // 8 independent gathers, front-batched (MLP=8), L2-only
    float4 v[ROWS_PER_CTA];
#pragma unroll
    for (int r = 0; r < ROWS_PER_CTA; r++)
        v[r] = ldcg_f4(&emb[src[r] * VEC_PER_ROW + t]);

    // 8 coalesced streaming stores (evict-first: protect the table in L2)
#pragma unroll
    for (int r = 0; r < ROWS_PER_CTA; r++)
        stcs_f4(&out[(long long)(base + r) * VEC_PER_ROW + t], v[r]);
}

extern "C" void kernel_launch(void* const* d_in, const int* in_sizes, int n_in,
                              void* d_out, int out_size)
{
    const int*   x   = (const int*)d_in[0];          // [4, 2048] int32 indices
    const float* emb = (const float*)d_in[1];        // [32000, 1024] fp32
    float*       out = (float*)d_out;                // [4, 2048, 1024] fp32

    const int n_rows = in_sizes[0];                  // 8192
    const int n_cta  = n_rows / ROWS_PER_CTA;        // 1024

    embedding_gather_kernel<<<n_cta, 256>>>(
        x, (const float4*)emb, (float4*)out);
}